// round 4
// baseline (speedup 1.0000x reference)
#include <cuda_runtime.h>
#include <cstdint>

#define BATCH 32
#define HH 512
#define WW 512
#define WPR 16            // u32 words per row (512 bits)
#define RPB 8             // rows per CTA in phase A
#define NBLK_Y (HH / RPB) // 64

// ---------------- global scratch (no allocation allowed) ----------------
__device__ __align__(16) unsigned g_maskP[BATCH * HH * WPR];
__device__ __align__(16) unsigned g_maskG[BATCH * HH * WPR];
__device__ double g_sums[BATCH][3];   // 0: sum p, 1: sum g, 2: sum p*g
__device__ int    g_cnt[BATCH][9];    // pe,ge,pei, pm,gm,pmi, pj,gj,pji
__device__ int    g_dist[2][BATCH];   // sum of clamped chebyshev distances
__device__ int    g_non[2][BATCH];    // count of target-on pixels

// ---------------- zero accumulators ----------------
__global__ void zero_kernel() {
    int t = threadIdx.x;
    if (t < BATCH * 3) ((double*)g_sums)[t] = 0.0;
    if (t < BATCH * 9) ((int*)g_cnt)[t] = 0;
}

// ---------------- phase A: sums, structural counters, bitmasks ----------------
__global__ void __launch_bounds__(512) phaseA(const float* __restrict__ pred,
                                              const float* __restrict__ gt) {
    __shared__ float sp[RPB + 2][WW];
    __shared__ float sg[RPB + 2][WW];
    __shared__ double rd[16][3];
    __shared__ int    ri[16][9];

    int blk = blockIdx.x;
    int b   = blk / NBLK_Y;
    int r0  = (blk % NBLK_Y) * RPB;
    int x   = threadIdx.x;            // column 0..511

    const float* pb = pred + (size_t)b * HH * WW;
    const float* gb = gt   + (size_t)b * HH * WW;

    #pragma unroll
    for (int yy = 0; yy < RPB + 2; yy++) {
        int r = r0 - 1 + yy;
        float pv = 0.f, gv = 0.f;
        if (r >= 0 && r < HH) { pv = pb[r * WW + x]; gv = gb[r * WW + x]; }
        sp[yy][x] = pv; sg[yy][x] = gv;
    }
    __syncthreads();

    float dp = 0.f, dg = 0.f, dpg = 0.f;
    int c0=0,c1=0,c2=0,c3=0,c4=0,c5=0,c6=0,c7=0,c8=0;

    // rolling 3-wide horizontal row sums (for gt these are exact small ints)
    float rsp0, rsp1, rsp2, rsg0, rsg1, rsg2;
    {
        float l, r;
        l = (x > 0) ? sp[0][x-1] : 0.f;  r = (x < WW-1) ? sp[0][x+1] : 0.f;
        rsp0 = l + sp[0][x] + r;
        l = (x > 0) ? sg[0][x-1] : 0.f;  r = (x < WW-1) ? sg[0][x+1] : 0.f;
        rsg0 = l + sg[0][x] + r;
        l = (x > 0) ? sp[1][x-1] : 0.f;  r = (x < WW-1) ? sp[1][x+1] : 0.f;
        rsp1 = l + sp[1][x] + r;
        l = (x > 0) ? sg[1][x-1] : 0.f;  r = (x < WW-1) ? sg[1][x+1] : 0.f;
        rsg1 = l + sg[1][x] + r;
    }

    #pragma unroll
    for (int y = 0; y < RPB; y++) {
        int yy = y + 1;
        {
            float l, r;
            l = (x > 0) ? sp[yy+1][x-1] : 0.f;  r = (x < WW-1) ? sp[yy+1][x+1] : 0.f;
            rsp2 = l + sp[yy+1][x] + r;
            l = (x > 0) ? sg[yy+1][x-1] : 0.f;  r = (x < WW-1) ? sg[yy+1][x+1] : 0.f;
            rsg2 = l + sg[yy+1][x] + r;
        }
        float p = sp[yy][x];
        float g = sg[yy][x];
        float np = (rsp0 + rsp1 + rsp2) - p;   // 8-neighbor sum (pred, continuous)
        float ng = (rsg0 + rsg1 + rsg2) - g;   // 8-neighbor sum (gt, exact int)
        bool pon = p > 0.5f, gon = g > 0.5f;

        dp += p; dg += g; dpg += p * g;

        bool pe = pon && (np == 1.f), pm = pon && (np == 2.f), pj = pon && (np > 2.f);
        bool ge = gon && (ng == 1.f), gm = gon && (ng == 2.f), gj = gon && (ng > 2.f);
        c0 += pe; c1 += ge; c2 += (pe && ge);
        c3 += pm; c4 += gm; c5 += (pm && gm);
        c6 += pj; c7 += gj; c8 += (pj && gj);

        unsigned mp = __ballot_sync(0xffffffffu, pon);
        unsigned mg = __ballot_sync(0xffffffffu, gon);
        if ((x & 31) == 0) {
            int w = x >> 5;
            g_maskP[((size_t)b * HH + r0 + y) * WPR + w] = mp;
            g_maskG[((size_t)b * HH + r0 + y) * WPR + w] = mg;
        }
        rsp0 = rsp1; rsp1 = rsp2;
        rsg0 = rsg1; rsg1 = rsg2;
    }

    // block reduce: 3 doubles + 9 ints
    double a0 = dp, a1 = dg, a2 = dpg;
    int cc[9] = {c0,c1,c2,c3,c4,c5,c6,c7,c8};
    #pragma unroll
    for (int o = 16; o > 0; o >>= 1) {
        a0 += __shfl_down_sync(0xffffffffu, a0, o);
        a1 += __shfl_down_sync(0xffffffffu, a1, o);
        a2 += __shfl_down_sync(0xffffffffu, a2, o);
        #pragma unroll
        for (int i = 0; i < 9; i++) cc[i] += __shfl_down_sync(0xffffffffu, cc[i], o);
    }
    int wid = threadIdx.x >> 5, lane = threadIdx.x & 31;
    if (lane == 0) {
        rd[wid][0] = a0; rd[wid][1] = a1; rd[wid][2] = a2;
        #pragma unroll
        for (int i = 0; i < 9; i++) ri[wid][i] = cc[i];
    }
    __syncthreads();
    if (wid == 0) {
        double b0 = (lane < 16) ? rd[lane][0] : 0.0;
        double b1 = (lane < 16) ? rd[lane][1] : 0.0;
        double b2 = (lane < 16) ? rd[lane][2] : 0.0;
        int bi[9];
        #pragma unroll
        for (int i = 0; i < 9; i++) bi[i] = (lane < 16) ? ri[lane][i] : 0;
        #pragma unroll
        for (int o = 8; o > 0; o >>= 1) {
            b0 += __shfl_down_sync(0xffffffffu, b0, o);
            b1 += __shfl_down_sync(0xffffffffu, b1, o);
            b2 += __shfl_down_sync(0xffffffffu, b2, o);
            #pragma unroll
            for (int i = 0; i < 9; i++) bi[i] += __shfl_down_sync(0xffffffffu, bi[i], o);
        }
        if (lane == 0) {
            atomicAdd(&g_sums[b][0], b0);
            atomicAdd(&g_sums[b][1], b1);
            atomicAdd(&g_sums[b][2], b2);
            #pragma unroll
            for (int i = 0; i < 9; i++) atomicAdd(&g_cnt[b][i], bi[i]);
        }
    }
}

// ---------------- phase B: bit-packed chebyshev distance sums ----------------
// sum_dist = N_on + sum_{d=1..9} popcount(tgt_on & ~dilate_d(ref_on))
__global__ void __launch_bounds__(512) phaseB() {
    extern __shared__ unsigned long long sh[];
    unsigned long long* T  = sh;           // 4096 u64 (512 rows x 8)
    unsigned long long* A  = sh + 4096;
    unsigned long long* Bu = sh + 8192;

    int cid = blockIdx.x;                  // 0..63
    int b   = cid & 31;
    int dir = cid >> 5;                    // 0: p2g (tgt=pred), 1: g2p (tgt=gt)

    const unsigned long long* tgt =
        (const unsigned long long*)(dir == 0 ? g_maskP : g_maskG) + (size_t)b * HH * 8;
    const unsigned long long* ref =
        (const unsigned long long*)(dir == 0 ? g_maskG : g_maskP) + (size_t)b * HH * 8;

    int t = threadIdx.x;
    int non = 0;
    for (int k = t; k < 4096; k += 512) {
        unsigned long long tv = tgt[k];
        T[k] = tv;
        A[k] = ref[k];
        non += __popcll(tv);
    }
    __syncthreads();

    int cntNot = 0;
    for (int d = 1; d <= 9; d++) {
        // horizontal dilation: Bu = Hdil(A)
        #pragma unroll
        for (int k = t; k < 4096; k += 512) {
            int j = k & 7;
            unsigned long long v = A[k];
            unsigned long long h = v | (v << 1) | (v >> 1);
            if (j > 0) h |= A[k - 1] >> 63;
            if (j < 7) h |= A[k + 1] << 63;
            Bu[k] = h;
        }
        __syncthreads();
        // vertical dilation: A = Vdil(Bu), accumulate uncovered target bits
        #pragma unroll
        for (int k = t; k < 4096; k += 512) {
            int r = k >> 3;
            unsigned long long v = Bu[k];
            if (r > 0)      v |= Bu[k - 8];
            if (r < HH - 1) v |= Bu[k + 8];
            A[k] = v;
            cntNot += __popcll(T[k] & ~v);
        }
        __syncthreads();
    }

    // block reduce non / cntNot
    #pragma unroll
    for (int o = 16; o > 0; o >>= 1) {
        non    += __shfl_down_sync(0xffffffffu, non, o);
        cntNot += __shfl_down_sync(0xffffffffu, cntNot, o);
    }
    int* ired = (int*)sh;   // safe: all data consumed, after sync
    int wid = t >> 5, lane = t & 31;
    if (lane == 0) { ired[wid * 2] = non; ired[wid * 2 + 1] = cntNot; }
    __syncthreads();
    if (t == 0) {
        int N = 0, C = 0;
        for (int w = 0; w < 16; w++) { N += ired[w * 2]; C += ired[w * 2 + 1]; }
        g_non[dir][b]  = N;
        g_dist[dir][b] = N + C;
    }
}

// ---------------- phase C: final combine ----------------
__global__ void phaseC(float* out) {
    int b = threadIdx.x;   // 32 threads
    double dice_t = 0.0, s_t = 0.0, m_t = 0.0;
    if (b < BATCH) {
        double psum  = g_sums[b][0];
        double gsum  = g_sums[b][1];
        double inter = g_sums[b][2];
        dice_t = (2.0 * inter + 1.0) / (psum + gsum + 1.0);

        double pe = g_cnt[b][0], ge = g_cnt[b][1], pei = g_cnt[b][2];
        double pm = g_cnt[b][3], gm = g_cnt[b][4], pmi = g_cnt[b][5];
        double pj = g_cnt[b][6], gj = g_cnt[b][7], pji = g_cnt[b][8];
        double e_iou = (pei + 1.0) / (pe + ge - pei + 1.0);
        double m_iou = (pmi + 1.0) / (pm + gm - pmi + 1.0);
        double j_iou = (pji + 1.0) / (pj + gj - pji + 1.0);
        double total = ge + gj + gm + 1.0;
        s_t = 1.0 - (ge * e_iou + gj * j_iou + gm * m_iou) / total;

        double p2g = (double)g_dist[0][b] / ((double)g_non[0][b] + 1.0);
        double g2p = (double)g_dist[1][b] / ((double)g_non[1][b] + 1.0);
        m_t = ((p2g + g2p) * 0.5) / 10.0;
    }
    #pragma unroll
    for (int o = 16; o > 0; o >>= 1) {
        dice_t += __shfl_down_sync(0xffffffffu, dice_t, o);
        s_t    += __shfl_down_sync(0xffffffffu, s_t, o);
        m_t    += __shfl_down_sync(0xffffffffu, m_t, o);
    }
    if (b == 0) {
        double dice_loss = 1.0 - dice_t / (double)BATCH;
        double s = s_t / (double)BATCH;
        double m = m_t / (double)BATCH;
        double avg = (dice_loss + s + m) / 3.0;
        double r = dice_loss / (dice_loss + 1.0) * avg
                 + s / (s + 1.0) * avg
                 + m / (m + 1.0) * avg;
        out[0] = (float)r;
    }
}

// ---------------- launch ----------------
extern "C" void kernel_launch(void* const* d_in, const int* in_sizes, int n_in,
                              void* d_out, int out_size) {
    const float* pred = (const float*)d_in[0];
    const float* gt   = (const float*)d_in[1];
    (void)in_sizes; (void)n_in; (void)out_size;

    cudaFuncSetAttribute(phaseB, cudaFuncAttributeMaxDynamicSharedMemorySize, 3 * 4096 * 8);

    zero_kernel<<<1, 288>>>();
    phaseA<<<BATCH * NBLK_Y, 512>>>(pred, gt);
    phaseB<<<64, 512, 3 * 4096 * 8>>>();
    phaseC<<<1, 32>>>((float*)d_out);
}

// round 7
// speedup vs baseline: 2.0640x; 2.0640x over previous
#include <cuda_runtime.h>
#include <cstdint>

#define BATCH 32
#define HH 512
#define WW 512
#define WPR 16              // u32 words per row (512 bits)
#define RPB 16              // rows per CTA in phase A
#define NBLK_Y (HH / RPB)   // 32
#define PITCH 520           // padded shared row pitch (floats)

// ---------------- global scratch (no allocation allowed) ----------------
__device__ __align__(16) unsigned g_maskP[BATCH * HH * WPR];
__device__ __align__(16) unsigned g_maskG[BATCH * HH * WPR];
__device__ double g_sums[BATCH][3];   // 0: sum p, 1: sum g, 2: sum p*g
__device__ int    g_cnt[BATCH][9];    // pe,ge,pei, pm,gm,pmi, pj,gj,pji
__device__ int    g_dist[2][BATCH];   // sum of clamped chebyshev distances
__device__ int    g_non[2][BATCH];    // count of target-on pixels

// ---------------- phase A: sums, structural counters, bitmasks ----------------
__global__ void __launch_bounds__(512) phaseA(const float* __restrict__ pred,
                                              const float* __restrict__ gt) {
    extern __shared__ float smemA[];
    float* sp = smemA;                        // (RPB+2) x PITCH
    float* sg = smemA + (RPB + 2) * PITCH;
    __shared__ float rf[16][3];
    __shared__ int   ri[16][5];

    int blk = blockIdx.x;
    int b   = blk >> 5;                 // / NBLK_Y (=32)
    int r0  = (blk & 31) * RPB;
    int x   = threadIdx.x;              // column 0..511
    int xx  = x + 1;                    // padded index

    const float* pb = pred + (size_t)b * HH * WW;
    const float* gb = gt   + (size_t)b * HH * WW;

    #pragma unroll
    for (int yy = 0; yy < RPB + 2; yy++) {
        int r = r0 - 1 + yy;
        float pv = 0.f, gv = 0.f;
        if (r >= 0 && r < HH) { pv = pb[r * WW + x]; gv = gb[r * WW + x]; }
        sp[yy * PITCH + xx] = pv; sg[yy * PITCH + xx] = gv;
    }
    if (x == 0) {
        #pragma unroll
        for (int yy = 0; yy < RPB + 2; yy++) {
            sp[yy * PITCH] = 0.f;          sg[yy * PITCH] = 0.f;
            sp[yy * PITCH + WW + 1] = 0.f; sg[yy * PITCH + WW + 1] = 0.f;
        }
    }
    __syncthreads();

    float dp = 0.f, dg = 0.f, dpg = 0.f;
    int c0=0,c1=0,c2=0,c3=0,c4=0,c5=0,c6=0,c7=0,c8=0;

    // rolling 3-wide horizontal row sums (for gt these are exact small ints)
    float rsp0 = sp[xx-1] + sp[xx] + sp[xx+1];
    float rsg0 = sg[xx-1] + sg[xx] + sg[xx+1];
    float rsp1 = sp[PITCH+xx-1] + sp[PITCH+xx] + sp[PITCH+xx+1];
    float rsg1 = sg[PITCH+xx-1] + sg[PITCH+xx] + sg[PITCH+xx+1];
    float rsp2, rsg2;

    #pragma unroll
    for (int y = 0; y < RPB; y++) {
        int yy = y + 1;
        rsp2 = sp[(yy+1)*PITCH+xx-1] + sp[(yy+1)*PITCH+xx] + sp[(yy+1)*PITCH+xx+1];
        rsg2 = sg[(yy+1)*PITCH+xx-1] + sg[(yy+1)*PITCH+xx] + sg[(yy+1)*PITCH+xx+1];
        float p = sp[yy*PITCH+xx];
        float g = sg[yy*PITCH+xx];
        float np = (rsp0 + rsp1 + rsp2) - p;   // 8-neighbor sum (pred, continuous)
        float ng = (rsg0 + rsg1 + rsg2) - g;   // 8-neighbor sum (gt, exact int)
        bool pon = p > 0.5f, gon = g > 0.5f;

        dp += p; dg += g; dpg += p * g;

        bool pe = pon && (np == 1.f), pm = pon && (np == 2.f), pj = pon && (np > 2.f);
        bool ge = gon && (ng == 1.f), gm = gon && (ng == 2.f), gj = gon && (ng > 2.f);
        c0 += pe; c1 += ge; c2 += (pe && ge);
        c3 += pm; c4 += gm; c5 += (pm && gm);
        c6 += pj; c7 += gj; c8 += (pj && gj);

        unsigned mp = __ballot_sync(0xffffffffu, pon);
        unsigned mg = __ballot_sync(0xffffffffu, gon);
        if ((x & 31) == 0) {
            int w = x >> 5;
            g_maskP[((size_t)b * HH + r0 + y) * WPR + w] = mp;
            g_maskG[((size_t)b * HH + r0 + y) * WPR + w] = mg;
        }
        rsp0 = rsp1; rsp1 = rsp2;
        rsg0 = rsg1; rsg1 = rsg2;
    }

    // pack 9 small counters (<=16 per thread, <=8192 per block) into u16 pairs
    int u0 = c0 | (c1 << 16);
    int u1 = c2 | (c3 << 16);
    int u2 = c4 | (c5 << 16);
    int u3 = c6 | (c7 << 16);
    int u4 = c8;
    float a0 = dp, a1 = dg, a2 = dpg;

    #pragma unroll
    for (int o = 16; o > 0; o >>= 1) {
        a0 += __shfl_down_sync(0xffffffffu, a0, o);
        a1 += __shfl_down_sync(0xffffffffu, a1, o);
        a2 += __shfl_down_sync(0xffffffffu, a2, o);
        u0 += __shfl_down_sync(0xffffffffu, u0, o);
        u1 += __shfl_down_sync(0xffffffffu, u1, o);
        u2 += __shfl_down_sync(0xffffffffu, u2, o);
        u3 += __shfl_down_sync(0xffffffffu, u3, o);
        u4 += __shfl_down_sync(0xffffffffu, u4, o);
    }
    int wid = threadIdx.x >> 5, lane = threadIdx.x & 31;
    if (lane == 0) {
        rf[wid][0] = a0; rf[wid][1] = a1; rf[wid][2] = a2;
        ri[wid][0] = u0; ri[wid][1] = u1; ri[wid][2] = u2; ri[wid][3] = u3; ri[wid][4] = u4;
    }
    __syncthreads();
    if (wid == 0) {
        float b0 = (lane < 16) ? rf[lane][0] : 0.f;
        float b1 = (lane < 16) ? rf[lane][1] : 0.f;
        float b2 = (lane < 16) ? rf[lane][2] : 0.f;
        int v0 = (lane < 16) ? ri[lane][0] : 0;
        int v1 = (lane < 16) ? ri[lane][1] : 0;
        int v2 = (lane < 16) ? ri[lane][2] : 0;
        int v3 = (lane < 16) ? ri[lane][3] : 0;
        int v4 = (lane < 16) ? ri[lane][4] : 0;
        #pragma unroll
        for (int o = 8; o > 0; o >>= 1) {
            b0 += __shfl_down_sync(0xffffffffu, b0, o);
            b1 += __shfl_down_sync(0xffffffffu, b1, o);
            b2 += __shfl_down_sync(0xffffffffu, b2, o);
            v0 += __shfl_down_sync(0xffffffffu, v0, o);
            v1 += __shfl_down_sync(0xffffffffu, v1, o);
            v2 += __shfl_down_sync(0xffffffffu, v2, o);
            v3 += __shfl_down_sync(0xffffffffu, v3, o);
            v4 += __shfl_down_sync(0xffffffffu, v4, o);
        }
        if (lane == 0) {
            atomicAdd(&g_sums[b][0], (double)b0);
            atomicAdd(&g_sums[b][1], (double)b1);
            atomicAdd(&g_sums[b][2], (double)b2);
            atomicAdd(&g_cnt[b][0], v0 & 0xffff);
            atomicAdd(&g_cnt[b][1], v0 >> 16);
            atomicAdd(&g_cnt[b][2], v1 & 0xffff);
            atomicAdd(&g_cnt[b][3], v1 >> 16);
            atomicAdd(&g_cnt[b][4], v2 & 0xffff);
            atomicAdd(&g_cnt[b][5], v2 >> 16);
            atomicAdd(&g_cnt[b][6], v3 & 0xffff);
            atomicAdd(&g_cnt[b][7], v3 >> 16);
            atomicAdd(&g_cnt[b][8], v4);
        }
    }
}

// ---------------- phase B: bit-packed chebyshev distance sums ----------------
// sum_dist = N_on + sum_{d=1..9} popcount(tgt_on & ~dilate_d(ref_on))
// Early exit: per-round uncovered count is monotone non-increasing; once a
// round contributes 0, all later rounds contribute 0.
__global__ void __launch_bounds__(512) phaseB() {
    extern __shared__ unsigned long long sh[];
    unsigned long long* T  = sh;           // 4096 u64 (512 rows x 8)
    unsigned long long* A  = sh + 4096;
    unsigned long long* Bu = sh + 8192;

    int cid = blockIdx.x;                  // 0..63
    int b   = cid & 31;
    int dir = cid >> 5;                    // 0: p2g (tgt=pred), 1: g2p (tgt=gt)

    const unsigned long long* tgt =
        (const unsigned long long*)(dir == 0 ? g_maskP : g_maskG) + (size_t)b * HH * 8;
    const unsigned long long* ref =
        (const unsigned long long*)(dir == 0 ? g_maskG : g_maskP) + (size_t)b * HH * 8;

    int t = threadIdx.x;
    int non = 0;
    for (int k = t; k < 4096; k += 512) {
        unsigned long long tv = tgt[k];
        T[k] = tv;
        A[k] = ref[k];
        non += __popcll(tv);
    }
    __syncthreads();

    int cntNot = 0;
    for (int d = 1; d <= 9; d++) {
        // horizontal dilation: Bu = Hdil(A)
        #pragma unroll
        for (int k = t; k < 4096; k += 512) {
            int j = k & 7;
            unsigned long long v = A[k];
            unsigned long long h = v | (v << 1) | (v >> 1);
            if (j > 0) h |= A[k - 1] >> 63;
            if (j < 7) h |= A[k + 1] << 63;
            Bu[k] = h;
        }
        __syncthreads();
        // vertical dilation: A = Vdil(Bu), accumulate uncovered target bits
        int roundCnt = 0;
        #pragma unroll
        for (int k = t; k < 4096; k += 512) {
            int r = k >> 3;
            unsigned long long v = Bu[k];
            if (r > 0)      v |= Bu[k - 8];
            if (r < HH - 1) v |= Bu[k + 8];
            A[k] = v;
            roundCnt += __popcll(T[k] & ~v);
        }
        cntNot += roundCnt;
        if (__syncthreads_count(roundCnt) == 0) break;   // also the barrier
    }

    // block reduce non / cntNot
    #pragma unroll
    for (int o = 16; o > 0; o >>= 1) {
        non    += __shfl_down_sync(0xffffffffu, non, o);
        cntNot += __shfl_down_sync(0xffffffffu, cntNot, o);
    }
    int* ired = (int*)sh;   // safe: all smem data consumed, barrier passed
    int wid = t >> 5, lane = t & 31;
    if (lane == 0) { ired[wid * 2] = non; ired[wid * 2 + 1] = cntNot; }
    __syncthreads();
    if (t == 0) {
        int N = 0, C = 0;
        for (int w = 0; w < 16; w++) { N += ired[w * 2]; C += ired[w * 2 + 1]; }
        g_non[dir][b]  = N;
        g_dist[dir][b] = N + C;
    }
}

// ---------------- phase C: final combine (fp32) + re-zero accumulators ----------------
__global__ void phaseC(float* out) {
    int b = threadIdx.x;   // 32 threads
    float dice_t = 0.f, s_t = 0.f, m_t = 0.f;
    if (b < BATCH) {
        float psum  = (float)g_sums[b][0];
        float gsum  = (float)g_sums[b][1];
        float inter = (float)g_sums[b][2];
        dice_t = __fdividef(2.f * inter + 1.f, psum + gsum + 1.f);

        float pe = (float)g_cnt[b][0], ge = (float)g_cnt[b][1], pei = (float)g_cnt[b][2];
        float pm = (float)g_cnt[b][3], gm = (float)g_cnt[b][4], pmi = (float)g_cnt[b][5];
        float pj = (float)g_cnt[b][6], gj = (float)g_cnt[b][7], pji = (float)g_cnt[b][8];
        float e_iou = __fdividef(pei + 1.f, pe + ge - pei + 1.f);
        float m_iou = __fdividef(pmi + 1.f, pm + gm - pmi + 1.f);
        float j_iou = __fdividef(pji + 1.f, pj + gj - pji + 1.f);
        float total = ge + gj + gm + 1.f;
        s_t = 1.f - __fdividef(ge * e_iou + gj * j_iou + gm * m_iou, total);

        float p2g = __fdividef((float)g_dist[0][b], (float)g_non[0][b] + 1.f);
        float g2p = __fdividef((float)g_dist[1][b], (float)g_non[1][b] + 1.f);
        m_t = ((p2g + g2p) * 0.5f) * 0.1f;

        // re-zero accumulators for the next graph replay (each thread owns slot b)
        g_sums[b][0] = 0.0; g_sums[b][1] = 0.0; g_sums[b][2] = 0.0;
        #pragma unroll
        for (int i = 0; i < 9; i++) g_cnt[b][i] = 0;
    }
    #pragma unroll
    for (int o = 16; o > 0; o >>= 1) {
        dice_t += __shfl_down_sync(0xffffffffu, dice_t, o);
        s_t    += __shfl_down_sync(0xffffffffu, s_t, o);
        m_t    += __shfl_down_sync(0xffffffffu, m_t, o);
    }
    if (b == 0) {
        float dice_loss = 1.f - dice_t * (1.f / BATCH);
        float s = s_t * (1.f / BATCH);
        float m = m_t * (1.f / BATCH);
        float avg = (dice_loss + s + m) * (1.f / 3.f);
        float r = __fdividef(dice_loss, dice_loss + 1.f) * avg
                + __fdividef(s, s + 1.f) * avg
                + __fdividef(m, m + 1.f) * avg;
        out[0] = r;
    }
}

// ---------------- launch ----------------
extern "C" void kernel_launch(void* const* d_in, const int* in_sizes, int n_in,
                              void* d_out, int out_size) {
    const float* pred = (const float*)d_in[0];
    const float* gt   = (const float*)d_in[1];
    (void)in_sizes; (void)n_in; (void)out_size;

    const int ASMEM = 2 * (RPB + 2) * PITCH * sizeof(float);   // 74880 bytes
    cudaFuncSetAttribute(phaseA, cudaFuncAttributeMaxDynamicSharedMemorySize, ASMEM);
    cudaFuncSetAttribute(phaseB, cudaFuncAttributeMaxDynamicSharedMemorySize, 3 * 4096 * 8);

    phaseA<<<BATCH * NBLK_Y, 512, ASMEM>>>(pred, gt);
    phaseB<<<64, 512, 3 * 4096 * 8>>>();
    phaseC<<<1, 32>>>((float*)d_out);
}